// round 10
// baseline (speedup 1.0000x reference)
#include <cuda_runtime.h>
#include <cuda_bf16.h>
#include <cuda_fp16.h>
#include <cstdint>

// Problem constants (fixed by the reference)
#define BB 2
#define TT 2048
#define DD 1024
#define HH 16
#define DKK 64
#define TD3 3072    // 3*D
#define MM (BB*TT)  // 4096 rows
#define KK 1024     // GEMM K for both projections

// softmax scale folded with log2(e): exp(x*0.125) = 2^(x*0.125*log2e)
#define QK_SCALE 0.18033688011112042f

// ---------------------------------------------------------------------------
// Scratch (allocation-free rule: __device__ globals)
// ---------------------------------------------------------------------------
__device__ __half g_qkv[MM * TD3];           // qkv fp16
__device__ __half g_x[MM * KK];              // x fp16
__device__ __half g_y[MM * KK];              // attention out fp16
__device__ __half g_wqh[TD3 * KK];           // W_qkv^T fp16, [N][K]
__device__ __half g_woh[DD * KK];            // W_o^T fp16, [N][K]

// ---------------------------------------------------------------------------
// PTX helpers (plain sm_100-legal: cp.async + ldmatrix + mma.sync)
// ---------------------------------------------------------------------------
__device__ __forceinline__ uint32_t smem_u32(const void* p) {
    uint32_t a;
    asm("{ .reg .u64 t; cvta.to.shared.u64 t, %1; cvt.u32.u64 %0, t; }"
        : "=r"(a) : "l"(p));
    return a;
}
__device__ __forceinline__ void cp16(uint32_t dst, const void* src) {
    asm volatile("cp.async.cg.shared.global [%0], [%1], 16;" :: "r"(dst), "l"(src));
}
__device__ __forceinline__ void cp_commit() {
    asm volatile("cp.async.commit_group;" ::: "memory");
}
template <int N>
__device__ __forceinline__ void cp_wait() {
    asm volatile("cp.async.wait_group %0;" :: "n"(N) : "memory");
}
__device__ __forceinline__ void ldm4(uint32_t* r, uint32_t addr) {
    asm volatile("ldmatrix.sync.aligned.m8n8.x4.shared.b16 {%0,%1,%2,%3}, [%4];"
                 : "=r"(r[0]), "=r"(r[1]), "=r"(r[2]), "=r"(r[3]) : "r"(addr));
}
__device__ __forceinline__ void ldm4t(uint32_t* r, uint32_t addr) {
    asm volatile("ldmatrix.sync.aligned.m8n8.x4.trans.shared.b16 {%0,%1,%2,%3}, [%4];"
                 : "=r"(r[0]), "=r"(r[1]), "=r"(r[2]), "=r"(r[3]) : "r"(addr));
}
// fp16 MMA
__device__ __forceinline__ void mma16816h(float* c, const uint32_t* a,
                                          const uint32_t* b) {
    asm volatile(
        "mma.sync.aligned.m16n8k16.row.col.f32.f16.f16.f32 "
        "{%0,%1,%2,%3}, {%4,%5,%6,%7}, {%8,%9}, {%0,%1,%2,%3};"
        : "+f"(c[0]), "+f"(c[1]), "+f"(c[2]), "+f"(c[3])
        : "r"(a[0]), "r"(a[1]), "r"(a[2]), "r"(a[3]), "r"(b[0]), "r"(b[1]));
}
__device__ __forceinline__ uint32_t pack_half(float a, float b) {
    __half2 t = __floats2half2_rn(a, b);             // .x = a (low)
    return *(uint32_t*)&t;
}

// ---------------------------------------------------------------------------
// Conversion kernels
// ---------------------------------------------------------------------------
struct __align__(8) h4 { __half v[4]; };

// fp32 -> fp16
__global__ __launch_bounds__(256) void convert_f32h(
    const float* __restrict__ src, __half* __restrict__ dst, int n)
{
    int i = (blockIdx.x * blockDim.x + threadIdx.x) * 4;
    if (i >= n) return;
    float4 v = *(const float4*)(src + i);
    h4 h;
    h.v[0] = __float2half_rn(v.x);
    h.v[1] = __float2half_rn(v.y);
    h.v[2] = __float2half_rn(v.z);
    h.v[3] = __float2half_rn(v.w);
    *(h4*)(dst + i) = h;
}

// W [K][N] fp32 -> Wt [N][K] fp16 (transpose)
__global__ __launch_bounds__(256) void transpose_h(
    const float* __restrict__ W, __half* __restrict__ T, int K, int N)
{
    __shared__ float t[32][33];
    int n0 = blockIdx.x * 32, k0 = blockIdx.y * 32;
    int tx = threadIdx.x, ty = threadIdx.y;
#pragma unroll
    for (int i = ty; i < 32; i += 8)
        t[i][tx] = W[(size_t)(k0 + i) * N + n0 + tx];
    __syncthreads();
#pragma unroll
    for (int i = ty; i < 32; i += 8)
        T[(size_t)(n0 + i) * K + k0 + tx] = __float2half_rn(t[tx][i]);
}

// ---------------------------------------------------------------------------
// fp16 single-pass GEMM: C = A @ B^T + bias.
// 128x128 tile / CTA, BK=32, 3-stage cp.async, one sync per chunk.
// ---------------------------------------------------------------------------
#define TILE_B 8192                    // 128 rows * 64 B
#define STAGE_B (2 * TILE_B)           // A, B
#define GSTAGES 3
#define GSMEM_BYTES (GSTAGES * STAGE_B)  // 49152
#define NCHUNK (KK / 32)               // 32

__device__ __forceinline__ uint32_t swz_off(int row, int chunk) {
    return (uint32_t)(row * 64 + ((chunk ^ ((row >> 1) & 3)) << 4));
}

__device__ __forceinline__ void load_stage(
    uint32_t sb, int s, int k0,
    const __half* __restrict__ A, const __half* __restrict__ Bh,
    int m0, int n0, int tid)
{
    uint32_t base = sb + (uint32_t)s * STAGE_B;
    const __half* srcs[2] = {A, Bh};
    int r0s[2] = {m0, n0};
#pragma unroll
    for (int t = 0; t < 2; t++) {
        const __half* p = srcs[t];
        int r0 = r0s[t];
        uint32_t tb = base + t * TILE_B;
#pragma unroll
        for (int i = 0; i < 2; i++) {
            int c = tid + i * 256;
            int row = c >> 2;
            int ch = c & 3;
            const void* g = p + (size_t)(r0 + row) * KK + k0 + ch * 8;
            cp16(tb + swz_off(row, ch), g);
        }
    }
    cp_commit();
}

template <bool HALF_OUT>
__global__ __launch_bounds__(256, 2) void gemm_mma(
    const __half* __restrict__ A, const __half* __restrict__ Bh,
    const float* __restrict__ bias, float* __restrict__ C,
    __half* __restrict__ Ch, int N)
{
    extern __shared__ char smem[];
    uint32_t sb = smem_u32(smem);
    const int tid = threadIdx.x;
    const int wid = tid >> 5;
    const int lane = tid & 31;
    const int warp_m = wid >> 1;
    const int warp_n = wid & 1;
    const int n0 = blockIdx.x * 128;
    const int m0 = blockIdx.y * 128;

    float acc[2][8][4];
#pragma unroll
    for (int i = 0; i < 2; i++)
#pragma unroll
        for (int j = 0; j < 8; j++)
#pragma unroll
            for (int k = 0; k < 4; k++) acc[i][j][k] = 0.f;

    load_stage(sb, 0, 0, A, Bh, m0, n0, tid);
    load_stage(sb, 1, 32, A, Bh, m0, n0, tid);

    for (int c = 0; c < NCHUNK; c++) {
        if (c == NCHUNK - 1) cp_wait<0>(); else cp_wait<1>();
        __syncthreads();
        // load c+2 into buffer of c-1 (all warps finished it before barrier)
        if (c + 2 < NCHUNK)
            load_stage(sb, (c + 2) % GSTAGES, (c + 2) * 32, A, Bh, m0, n0, tid);

        uint32_t abase = sb + (uint32_t)(c % GSTAGES) * STAGE_B;
#pragma unroll
        for (int ks = 0; ks < 2; ks++) {
            uint32_t ah[2][4], bh[4][4];
#pragma unroll
            for (int mt = 0; mt < 2; mt++) {
                int row = warp_m * 32 + mt * 16 + (lane & 15);
                int ch = ks * 2 + (lane >> 4);
                ldm4(ah[mt], abase + swz_off(row, ch));
            }
#pragma unroll
            for (int p = 0; p < 4; p++) {
                int row = warp_n * 64 + (p * 2 + (lane >> 4)) * 8 + (lane & 7);
                int ch = ks * 2 + ((lane >> 3) & 1);
                ldm4(bh[p], abase + TILE_B + swz_off(row, ch));
            }
#pragma unroll
            for (int mt = 0; mt < 2; mt++)
#pragma unroll
                for (int nt = 0; nt < 8; nt++)
                    mma16816h(acc[mt][nt], ah[mt], &bh[nt >> 1][(nt & 1) * 2]);
        }
    }

#pragma unroll
    for (int mt = 0; mt < 2; mt++) {
        int m = m0 + warp_m * 32 + mt * 16 + (lane >> 2);
#pragma unroll
        for (int nt = 0; nt < 8; nt++) {
            int n = n0 + warp_n * 64 + nt * 8 + (lane & 3) * 2;
            float b0 = bias[n], b1 = bias[n + 1];
            float f0 = acc[mt][nt][0] + b0, f1 = acc[mt][nt][1] + b1;
            float f2 = acc[mt][nt][2] + b0, f3 = acc[mt][nt][3] + b1;
            if (HALF_OUT) {
                *(uint32_t*)(Ch + (size_t)m * N + n) = pack_half(f0, f1);
                *(uint32_t*)(Ch + (size_t)(m + 8) * N + n) = pack_half(f2, f3);
            } else {
                float2 o0 = {f0, f1}, o1 = {f2, f3};
                *(float2*)(C + (size_t)m * N + n) = o0;
                *(float2*)(C + (size_t)(m + 8) * N + n) = o1;
            }
        }
    }
}

// ---------------------------------------------------------------------------
// Tensor-core flash attention (causal), fp16 single-pass.
// Softmax in log2 domain: P = 2^(s-m) computed with h2exp2 (fp16x2 MUFU,
// half the MUFU ops; result IS the PV a-fragment). 2 CTAs/SM (128-reg cap).
// ---------------------------------------------------------------------------
#define FA_TILE_B 8192                  // 64 rows * 128 B
#define FA_STAGE_B (2 * FA_TILE_B)      // K, V
#define FA_SMEM (2 * FA_STAGE_B)        // 32768

__device__ __forceinline__ uint32_t fswz(int row, int ch) {
    return (uint32_t)(row * 128 + ((ch ^ (row & 7)) << 4));
}

__device__ __forceinline__ void fa_load(
    uint32_t sb, int s, int k0, const __half* __restrict__ qkv,
    int b, int h, int tid)
{
    uint32_t base = sb + (uint32_t)s * FA_STAGE_B;
    int goff[2] = {1024, 2048};   // K, V
#pragma unroll
    for (int t = 0; t < 2; t++) {
        uint32_t tb = base + t * FA_TILE_B;
#pragma unroll
        for (int i = 0; i < 2; i++) {
            int idx = tid + i * 256;
            int row = idx >> 3;
            int ch = idx & 7;
            const void* g = qkv + (size_t)(b * TT + k0 + row) * TD3 + goff[t]
                          + h * 64 + ch * 8;
            cp16(tb + fswz(row, ch), g);
        }
    }
    cp_commit();
}

__global__ __launch_bounds__(256, 2) void flash_tc(
    const __half* __restrict__ qkv, __half* __restrict__ y)
{
    extern __shared__ char smem[];
    uint32_t sb = smem_u32(smem);
    const int tid = threadIdx.x;
    const int wid = tid >> 5;
    const int lane = tid & 31;
    const int qt = (int)gridDim.x - 1 - (int)blockIdx.x;   // big tiles first
    const int bh = blockIdx.y;
    const int b = bh >> 4;
    const int h = bh & 15;
    const int q0 = qt * 128;

    const int ntile = 2 * (qt + 1);
    fa_load(sb, 0, 0, qkv, b, h, tid);   // 1 group in flight

    // ---- Q fragments (fp16) straight from gmem ----
    uint32_t qf[4][4];
    {
        size_t r0g = (size_t)(b * TT + q0 + wid * 16 + (lane >> 2));
        const uint32_t* p0 = (const uint32_t*)(qkv + r0g * TD3 + h * 64);
        const uint32_t* p1 = (const uint32_t*)(qkv + (r0g + 8) * TD3 + h * 64);
        int c2 = lane & 3;
#pragma unroll
        for (int ks = 0; ks < 4; ks++) {
            qf[ks][0] = p0[ks * 8 + c2];
            qf[ks][1] = p1[ks * 8 + c2];
            qf[ks][2] = p0[ks * 8 + c2 + 4];
            qf[ks][3] = p1[ks * 8 + c2 + 4];
        }
    }

    float acc_o[8][4];
#pragma unroll
    for (int i = 0; i < 8; i++)
#pragma unroll
        for (int j = 0; j < 4; j++) acc_o[i][j] = 0.f;
    float mr0 = -1e30f, mr1 = -1e30f, lr0 = 0.f, lr1 = 0.f;

    for (int kt = 0; kt < ntile; kt++) {
        const int s = kt & 1;
        const int k0 = kt * 64;
        cp_wait<0>();
        __syncthreads();
        if (kt + 1 < ntile)
            fa_load(sb, s ^ 1, (kt + 1) * 64, qkv, b, h, tid);

        uint32_t Kb = sb + (uint32_t)s * FA_STAGE_B;
        uint32_t Vb = Kb + FA_TILE_B;

        // ---- S = Q K^T (single pass) ----
        float accs[8][4];
#pragma unroll
        for (int i = 0; i < 8; i++)
#pragma unroll
            for (int j = 0; j < 4; j++) accs[i][j] = 0.f;

#pragma unroll
        for (int ks = 0; ks < 4; ks++) {
            uint32_t kf[4][4];
#pragma unroll
            for (int j = 0; j < 4; j++) {
                int g = lane >> 3;
                int nt = 2 * j + (g >> 1);
                int kh = g & 1;
                int row = nt * 8 + (lane & 7);
                ldm4(kf[j], Kb + fswz(row, ks * 2 + kh));
            }
#pragma unroll
            for (int nt = 0; nt < 8; nt++)
                mma16816h(accs[nt], qf[ks], &kf[nt >> 1][(nt & 1) * 2]);
        }

        // ---- scale (log2 domain) + causal mask ----
        const int qrow0 = q0 + wid * 16 + (lane >> 2);
        const bool diag = (k0 + 63 > q0 + wid * 16);
#pragma unroll
        for (int nt = 0; nt < 8; nt++) {
#pragma unroll
            for (int c = 0; c < 4; c++) {
                float v = accs[nt][c] * QK_SCALE;
                if (diag) {
                    int col = k0 + nt * 8 + 2 * (lane & 3) + (c & 1);
                    int row = qrow0 + ((c >> 1) << 3);
                    if (col > row) v = -1e30f;
                }
                accs[nt][c] = v;
            }
        }

        // ---- online softmax (base-2) ----
        float mA = -1e30f, mB = -1e30f;
#pragma unroll
        for (int nt = 0; nt < 8; nt++) {
            mA = fmaxf(mA, fmaxf(accs[nt][0], accs[nt][1]));
            mB = fmaxf(mB, fmaxf(accs[nt][2], accs[nt][3]));
        }
        mA = fmaxf(mA, __shfl_xor_sync(0xffffffffu, mA, 1));
        mA = fmaxf(mA, __shfl_xor_sync(0xffffffffu, mA, 2));
        mB = fmaxf(mB, __shfl_xor_sync(0xffffffffu, mB, 1));
        mB = fmaxf(mB, __shfl_xor_sync(0xffffffffu, mB, 2));
        float mnA = fmaxf(mr0, mA), mnB = fmaxf(mr1, mB);
        float aA = exp2f(mr0 - mnA), aB = exp2f(mr1 - mnB);

        // P = 2^(s-m) in fp16x2 (h2exp2) — this IS the PV a-fragment.
        uint32_t pf[4][4];
        float psA = 0.f, psB = 0.f;
#pragma unroll
        for (int nt = 0; nt < 8; nt++) {
            __half2 e0 = h2exp2(__floats2half2_rn(accs[nt][0] - mnA,
                                                  accs[nt][1] - mnA));
            __half2 e1 = h2exp2(__floats2half2_rn(accs[nt][2] - mnB,
                                                  accs[nt][3] - mnB));
            pf[nt >> 1][(nt & 1) * 2 + 0] = *(uint32_t*)&e0;
            pf[nt >> 1][(nt & 1) * 2 + 1] = *(uint32_t*)&e1;
            float2 f0 = __half22float2(e0);
            float2 f1 = __half22float2(e1);
            psA += f0.x + f0.y;
            psB += f1.x + f1.y;
        }
        psA += __shfl_xor_sync(0xffffffffu, psA, 1);
        psA += __shfl_xor_sync(0xffffffffu, psA, 2);
        psB += __shfl_xor_sync(0xffffffffu, psB, 1);
        psB += __shfl_xor_sync(0xffffffffu, psB, 2);
        lr0 = lr0 * aA + psA;
        lr1 = lr1 * aB + psB;
        mr0 = mnA;
        mr1 = mnB;
#pragma unroll
        for (int nt = 0; nt < 8; nt++) {
            acc_o[nt][0] *= aA;
            acc_o[nt][1] *= aA;
            acc_o[nt][2] *= aB;
            acc_o[nt][3] *= aB;
        }

        // ---- O += P V (single pass), V frags via ldmatrix.trans ----
#pragma unroll
        for (int ks = 0; ks < 4; ks++) {
            uint32_t vf[4][4];
#pragma unroll
            for (int j = 0; j < 4; j++) {
                int g = lane >> 3;
                int nt = 2 * j + (g >> 1);
                int kh = g & 1;
                int row = ks * 16 + kh * 8 + (lane & 7);
                ldm4t(vf[j], Vb + fswz(row, nt));
            }
#pragma unroll
            for (int nt = 0; nt < 8; nt++)
                mma16816h(acc_o[nt], pf[ks], &vf[nt >> 1][(nt & 1) * 2]);
        }
    }

    // ---- epilogue: normalize, store fp16 y ----
    float invA = 1.f / lr0, invB = 1.f / lr1;
    size_t rA = (size_t)(b * TT + q0 + wid * 16 + (lane >> 2));
    size_t rB = rA + 8;
#pragma unroll
    for (int nt = 0; nt < 8; nt++) {
        int col = h * 64 + nt * 8 + 2 * (lane & 3);
        *(uint32_t*)(y + rA * DD + col) =
            pack_half(acc_o[nt][0] * invA, acc_o[nt][1] * invA);
        *(uint32_t*)(y + rB * DD + col) =
            pack_half(acc_o[nt][2] * invB, acc_o[nt][3] * invB);
    }
}

// ---------------------------------------------------------------------------
// Launch
// ---------------------------------------------------------------------------
extern "C" void kernel_launch(void* const* d_in, const int* in_sizes, int n_in,
                              void* d_out, int out_size)
{
    const float* x     = (const float*)d_in[0];
    const float* W_qkv = (const float*)d_in[1];
    const float* b_qkv = (const float*)d_in[2];
    const float* W_o   = (const float*)d_in[3];
    const float* b_o   = (const float*)d_in[4];
    float* out = (float*)d_out;

    __half *qkv, *xh, *yh, *wqh, *woh;
    cudaGetSymbolAddress((void**)&qkv, g_qkv);
    cudaGetSymbolAddress((void**)&xh, g_x);
    cudaGetSymbolAddress((void**)&yh, g_y);
    cudaGetSymbolAddress((void**)&wqh, g_wqh);
    cudaGetSymbolAddress((void**)&woh, g_woh);

    cudaFuncSetAttribute(gemm_mma<true>, cudaFuncAttributeMaxDynamicSharedMemorySize,
                         GSMEM_BYTES);
    cudaFuncSetAttribute(gemm_mma<false>, cudaFuncAttributeMaxDynamicSharedMemorySize,
                         GSMEM_BYTES);
    cudaFuncSetAttribute(flash_tc, cudaFuncAttributeMaxDynamicSharedMemorySize,
                         FA_SMEM);

    // conversions
    convert_f32h<<<(MM * KK / 4 + 255) / 256, 256>>>(x, xh, MM * KK);
    transpose_h<<<dim3(TD3 / 32, KK / 32), dim3(32, 8)>>>(W_qkv, wqh, KK, TD3);
    transpose_h<<<dim3(DD / 32, KK / 32), dim3(32, 8)>>>(W_o, woh, KK, DD);

    // 1) QKV projection (fp16 single pass) -> fp16 qkv
    gemm_mma<true><<<dim3(TD3 / 128, MM / 128), 256, GSMEM_BYTES>>>(
        xh, wqh, b_qkv, nullptr, qkv, TD3);

    // 2) causal flash attention (fp16, base-2 softmax, h2exp2) -> fp16 y
    flash_tc<<<dim3(TT / 128, BB * HH), 256, FA_SMEM>>>(qkv, yh);

    // 3) output projection (fp16 single pass) -> fp32 out
    gemm_mma<false><<<dim3(DD / 128, MM / 128), 256, GSMEM_BYTES>>>(
        yh, woh, b_o, out, nullptr, DD);
}

// round 11
// speedup vs baseline: 1.0768x; 1.0768x over previous
#include <cuda_runtime.h>
#include <cuda_bf16.h>
#include <cuda_fp16.h>
#include <cstdint>

// Problem constants (fixed by the reference)
#define BB 2
#define TT 2048
#define DD 1024
#define HH 16
#define DKK 64
#define TD3 3072    // 3*D
#define MM (BB*TT)  // 4096 rows
#define KK 1024     // GEMM K for both projections

// softmax scale folded with log2(e): exp(x*0.125) = 2^(x*0.125*log2e)
#define QK_SCALE 0.18033688011112042f

// ---------------------------------------------------------------------------
// Scratch (allocation-free rule: __device__ globals)
// ---------------------------------------------------------------------------
__device__ __half g_qkv[MM * TD3];           // qkv fp16
__device__ __half g_x[MM * KK];              // x fp16
__device__ __half g_y[MM * KK];              // attention out fp16
__device__ __half g_wqh[TD3 * KK];           // W_qkv^T fp16, [N][K]
__device__ __half g_woh[DD * KK];            // W_o^T fp16, [N][K]

// ---------------------------------------------------------------------------
// PTX helpers (plain sm_100-legal: cp.async + ldmatrix + mma.sync)
// ---------------------------------------------------------------------------
__device__ __forceinline__ uint32_t smem_u32(const void* p) {
    uint32_t a;
    asm("{ .reg .u64 t; cvta.to.shared.u64 t, %1; cvt.u32.u64 %0, t; }"
        : "=r"(a) : "l"(p));
    return a;
}
__device__ __forceinline__ void cp16(uint32_t dst, const void* src) {
    asm volatile("cp.async.cg.shared.global [%0], [%1], 16;" :: "r"(dst), "l"(src));
}
__device__ __forceinline__ void cp_commit() {
    asm volatile("cp.async.commit_group;" ::: "memory");
}
template <int N>
__device__ __forceinline__ void cp_wait() {
    asm volatile("cp.async.wait_group %0;" :: "n"(N) : "memory");
}
__device__ __forceinline__ void ldm4(uint32_t* r, uint32_t addr) {
    asm volatile("ldmatrix.sync.aligned.m8n8.x4.shared.b16 {%0,%1,%2,%3}, [%4];"
                 : "=r"(r[0]), "=r"(r[1]), "=r"(r[2]), "=r"(r[3]) : "r"(addr));
}
__device__ __forceinline__ void ldm4t(uint32_t* r, uint32_t addr) {
    asm volatile("ldmatrix.sync.aligned.m8n8.x4.trans.shared.b16 {%0,%1,%2,%3}, [%4];"
                 : "=r"(r[0]), "=r"(r[1]), "=r"(r[2]), "=r"(r[3]) : "r"(addr));
}
// fp16 MMA
__device__ __forceinline__ void mma16816h(float* c, const uint32_t* a,
                                          const uint32_t* b) {
    asm volatile(
        "mma.sync.aligned.m16n8k16.row.col.f32.f16.f16.f32 "
        "{%0,%1,%2,%3}, {%4,%5,%6,%7}, {%8,%9}, {%0,%1,%2,%3};"
        : "+f"(c[0]), "+f"(c[1]), "+f"(c[2]), "+f"(c[3])
        : "r"(a[0]), "r"(a[1]), "r"(a[2]), "r"(a[3]), "r"(b[0]), "r"(b[1]));
}
__device__ __forceinline__ uint32_t pack_half(float a, float b) {
    __half2 t = __floats2half2_rn(a, b);             // .x = a (low)
    return *(uint32_t*)&t;
}

// ---------------------------------------------------------------------------
// Conversion kernels
// ---------------------------------------------------------------------------
struct __align__(8) h4 { __half v[4]; };

// fp32 -> fp16
__global__ __launch_bounds__(256) void convert_f32h(
    const float* __restrict__ src, __half* __restrict__ dst, int n)
{
    int i = (blockIdx.x * blockDim.x + threadIdx.x) * 4;
    if (i >= n) return;
    float4 v = *(const float4*)(src + i);
    h4 h;
    h.v[0] = __float2half_rn(v.x);
    h.v[1] = __float2half_rn(v.y);
    h.v[2] = __float2half_rn(v.z);
    h.v[3] = __float2half_rn(v.w);
    *(h4*)(dst + i) = h;
}

// W [K][N] fp32 -> Wt [N][K] fp16 (transpose)
__global__ __launch_bounds__(256) void transpose_h(
    const float* __restrict__ W, __half* __restrict__ T, int K, int N)
{
    __shared__ float t[32][33];
    int n0 = blockIdx.x * 32, k0 = blockIdx.y * 32;
    int tx = threadIdx.x, ty = threadIdx.y;
#pragma unroll
    for (int i = ty; i < 32; i += 8)
        t[i][tx] = W[(size_t)(k0 + i) * N + n0 + tx];
    __syncthreads();
#pragma unroll
    for (int i = ty; i < 32; i += 8)
        T[(size_t)(n0 + i) * K + k0 + tx] = __float2half_rn(t[tx][i]);
}

// ---------------------------------------------------------------------------
// fp16 single-pass GEMM: C = A @ B^T + bias.
// 128x128 tile / CTA, BK=32, 3-stage cp.async, one sync per chunk.
// ---------------------------------------------------------------------------
#define TILE_B 8192                    // 128 rows * 64 B
#define STAGE_B (2 * TILE_B)           // A, B
#define GSTAGES 3
#define GSMEM_BYTES (GSTAGES * STAGE_B)  // 49152
#define NCHUNK (KK / 32)               // 32

__device__ __forceinline__ uint32_t swz_off(int row, int chunk) {
    return (uint32_t)(row * 64 + ((chunk ^ ((row >> 1) & 3)) << 4));
}

__device__ __forceinline__ void load_stage(
    uint32_t sb, int s, int k0,
    const __half* __restrict__ A, const __half* __restrict__ Bh,
    int m0, int n0, int tid)
{
    uint32_t base = sb + (uint32_t)s * STAGE_B;
    const __half* srcs[2] = {A, Bh};
    int r0s[2] = {m0, n0};
#pragma unroll
    for (int t = 0; t < 2; t++) {
        const __half* p = srcs[t];
        int r0 = r0s[t];
        uint32_t tb = base + t * TILE_B;
#pragma unroll
        for (int i = 0; i < 2; i++) {
            int c = tid + i * 256;
            int row = c >> 2;
            int ch = c & 3;
            const void* g = p + (size_t)(r0 + row) * KK + k0 + ch * 8;
            cp16(tb + swz_off(row, ch), g);
        }
    }
    cp_commit();
}

template <bool HALF_OUT>
__global__ __launch_bounds__(256, 2) void gemm_mma(
    const __half* __restrict__ A, const __half* __restrict__ Bh,
    const float* __restrict__ bias, float* __restrict__ C,
    __half* __restrict__ Ch, int N)
{
    extern __shared__ char smem[];
    uint32_t sb = smem_u32(smem);
    const int tid = threadIdx.x;
    const int wid = tid >> 5;
    const int lane = tid & 31;
    const int warp_m = wid >> 1;
    const int warp_n = wid & 1;
    const int n0 = blockIdx.x * 128;
    const int m0 = blockIdx.y * 128;

    float acc[2][8][4];
#pragma unroll
    for (int i = 0; i < 2; i++)
#pragma unroll
        for (int j = 0; j < 8; j++)
#pragma unroll
            for (int k = 0; k < 4; k++) acc[i][j][k] = 0.f;

    load_stage(sb, 0, 0, A, Bh, m0, n0, tid);
    load_stage(sb, 1, 32, A, Bh, m0, n0, tid);

    for (int c = 0; c < NCHUNK; c++) {
        if (c == NCHUNK - 1) cp_wait<0>(); else cp_wait<1>();
        __syncthreads();
        // load c+2 into buffer of c-1 (all warps finished it before barrier)
        if (c + 2 < NCHUNK)
            load_stage(sb, (c + 2) % GSTAGES, (c + 2) * 32, A, Bh, m0, n0, tid);

        uint32_t abase = sb + (uint32_t)(c % GSTAGES) * STAGE_B;
#pragma unroll
        for (int ks = 0; ks < 2; ks++) {
            uint32_t ah[2][4], bh[4][4];
#pragma unroll
            for (int mt = 0; mt < 2; mt++) {
                int row = warp_m * 32 + mt * 16 + (lane & 15);
                int ch = ks * 2 + (lane >> 4);
                ldm4(ah[mt], abase + swz_off(row, ch));
            }
#pragma unroll
            for (int p = 0; p < 4; p++) {
                int row = warp_n * 64 + (p * 2 + (lane >> 4)) * 8 + (lane & 7);
                int ch = ks * 2 + ((lane >> 3) & 1);
                ldm4(bh[p], abase + TILE_B + swz_off(row, ch));
            }
#pragma unroll
            for (int mt = 0; mt < 2; mt++)
#pragma unroll
                for (int nt = 0; nt < 8; nt++)
                    mma16816h(acc[mt][nt], ah[mt], &bh[nt >> 1][(nt & 1) * 2]);
        }
    }

#pragma unroll
    for (int mt = 0; mt < 2; mt++) {
        int m = m0 + warp_m * 32 + mt * 16 + (lane >> 2);
#pragma unroll
        for (int nt = 0; nt < 8; nt++) {
            int n = n0 + warp_n * 64 + nt * 8 + (lane & 3) * 2;
            float b0 = bias[n], b1 = bias[n + 1];
            float f0 = acc[mt][nt][0] + b0, f1 = acc[mt][nt][1] + b1;
            float f2 = acc[mt][nt][2] + b0, f3 = acc[mt][nt][3] + b1;
            if (HALF_OUT) {
                *(uint32_t*)(Ch + (size_t)m * N + n) = pack_half(f0, f1);
                *(uint32_t*)(Ch + (size_t)(m + 8) * N + n) = pack_half(f2, f3);
            } else {
                float2 o0 = {f0, f1}, o1 = {f2, f3};
                *(float2*)(C + (size_t)m * N + n) = o0;
                *(float2*)(C + (size_t)(m + 8) * N + n) = o1;
            }
        }
    }
}

// ---------------------------------------------------------------------------
// Tensor-core flash attention (causal), fp16 single-pass, base-2 softmax
// with h2exp2. BM=64 (4 warps, 128 threads) — small CTA for 3 CTAs/SM
// occupancy WITHOUT a register cap (no spills). BN=64 keys/iter.
// ---------------------------------------------------------------------------
#define FA_TILE_B 8192                  // 64 rows * 128 B
#define FA_STAGE_B (2 * FA_TILE_B)      // K, V
#define FA_SMEM (2 * FA_STAGE_B)        // 32768

__device__ __forceinline__ uint32_t fswz(int row, int ch) {
    return (uint32_t)(row * 128 + ((ch ^ (row & 7)) << 4));
}

__device__ __forceinline__ void fa_load(
    uint32_t sb, int s, int k0, const __half* __restrict__ qkv,
    int b, int h, int tid)
{
    uint32_t base = sb + (uint32_t)s * FA_STAGE_B;
    int goff[2] = {1024, 2048};   // K, V
#pragma unroll
    for (int t = 0; t < 2; t++) {
        uint32_t tb = base + t * FA_TILE_B;
#pragma unroll
        for (int i = 0; i < 4; i++) {
            int idx = tid + i * 128;      // 0..511
            int row = idx >> 3;
            int ch = idx & 7;
            const void* g = qkv + (size_t)(b * TT + k0 + row) * TD3 + goff[t]
                          + h * 64 + ch * 8;
            cp16(tb + fswz(row, ch), g);
        }
    }
    cp_commit();
}

__global__ __launch_bounds__(128) void flash_tc(
    const __half* __restrict__ qkv, __half* __restrict__ y)
{
    extern __shared__ char smem[];
    uint32_t sb = smem_u32(smem);
    const int tid = threadIdx.x;
    const int wid = tid >> 5;          // 0..3
    const int lane = tid & 31;
    const int qt = (int)gridDim.x - 1 - (int)blockIdx.x;   // big tiles first
    const int bh = blockIdx.y;
    const int b = bh >> 4;
    const int h = bh & 15;
    const int q0 = qt * 64;

    const int ntile = qt + 1;
    fa_load(sb, 0, 0, qkv, b, h, tid);   // 1 group in flight

    // ---- Q fragments (fp16) straight from gmem ----
    uint32_t qf[4][4];
    {
        size_t r0g = (size_t)(b * TT + q0 + wid * 16 + (lane >> 2));
        const uint32_t* p0 = (const uint32_t*)(qkv + r0g * TD3 + h * 64);
        const uint32_t* p1 = (const uint32_t*)(qkv + (r0g + 8) * TD3 + h * 64);
        int c2 = lane & 3;
#pragma unroll
        for (int ks = 0; ks < 4; ks++) {
            qf[ks][0] = p0[ks * 8 + c2];
            qf[ks][1] = p1[ks * 8 + c2];
            qf[ks][2] = p0[ks * 8 + c2 + 4];
            qf[ks][3] = p1[ks * 8 + c2 + 4];
        }
    }

    float acc_o[8][4];
#pragma unroll
    for (int i = 0; i < 8; i++)
#pragma unroll
        for (int j = 0; j < 4; j++) acc_o[i][j] = 0.f;
    float mr0 = -1e30f, mr1 = -1e30f, lr0 = 0.f, lr1 = 0.f;

    for (int kt = 0; kt < ntile; kt++) {
        const int s = kt & 1;
        const int k0 = kt * 64;
        cp_wait<0>();
        __syncthreads();
        if (kt + 1 < ntile)
            fa_load(sb, s ^ 1, (kt + 1) * 64, qkv, b, h, tid);

        uint32_t Kb = sb + (uint32_t)s * FA_STAGE_B;
        uint32_t Vb = Kb + FA_TILE_B;

        // ---- S = Q K^T (single pass) ----
        float accs[8][4];
#pragma unroll
        for (int i = 0; i < 8; i++)
#pragma unroll
            for (int j = 0; j < 4; j++) accs[i][j] = 0.f;

#pragma unroll
        for (int ks = 0; ks < 4; ks++) {
            uint32_t kf[4][4];
#pragma unroll
            for (int j = 0; j < 4; j++) {
                int g = lane >> 3;
                int nt = 2 * j + (g >> 1);
                int kh = g & 1;
                int row = nt * 8 + (lane & 7);
                ldm4(kf[j], Kb + fswz(row, ks * 2 + kh));
            }
#pragma unroll
            for (int nt = 0; nt < 8; nt++)
                mma16816h(accs[nt], qf[ks], &kf[nt >> 1][(nt & 1) * 2]);
        }

        // ---- scale (log2 domain) + causal mask ----
        const int qrow0 = q0 + wid * 16 + (lane >> 2);
        const bool diag = (k0 + 63 > q0 + wid * 16);
#pragma unroll
        for (int nt = 0; nt < 8; nt++) {
#pragma unroll
            for (int c = 0; c < 4; c++) {
                float v = accs[nt][c] * QK_SCALE;
                if (diag) {
                    int col = k0 + nt * 8 + 2 * (lane & 3) + (c & 1);
                    int row = qrow0 + ((c >> 1) << 3);
                    if (col > row) v = -1e30f;
                }
                accs[nt][c] = v;
            }
        }

        // ---- online softmax (base-2) ----
        float mA = -1e30f, mB = -1e30f;
#pragma unroll
        for (int nt = 0; nt < 8; nt++) {
            mA = fmaxf(mA, fmaxf(accs[nt][0], accs[nt][1]));
            mB = fmaxf(mB, fmaxf(accs[nt][2], accs[nt][3]));
        }
        mA = fmaxf(mA, __shfl_xor_sync(0xffffffffu, mA, 1));
        mA = fmaxf(mA, __shfl_xor_sync(0xffffffffu, mA, 2));
        mB = fmaxf(mB, __shfl_xor_sync(0xffffffffu, mB, 1));
        mB = fmaxf(mB, __shfl_xor_sync(0xffffffffu, mB, 2));
        float mnA = fmaxf(mr0, mA), mnB = fmaxf(mr1, mB);
        float aA = exp2f(mr0 - mnA), aB = exp2f(mr1 - mnB);

        // P = 2^(s-m) in fp16x2 (h2exp2) — this IS the PV a-fragment.
        uint32_t pf[4][4];
        float psA = 0.f, psB = 0.f;
#pragma unroll
        for (int nt = 0; nt < 8; nt++) {
            __half2 e0 = h2exp2(__floats2half2_rn(accs[nt][0] - mnA,
                                                  accs[nt][1] - mnA));
            __half2 e1 = h2exp2(__floats2half2_rn(accs[nt][2] - mnB,
                                                  accs[nt][3] - mnB));
            pf[nt >> 1][(nt & 1) * 2 + 0] = *(uint32_t*)&e0;
            pf[nt >> 1][(nt & 1) * 2 + 1] = *(uint32_t*)&e1;
            float2 f0 = __half22float2(e0);
            float2 f1 = __half22float2(e1);
            psA += f0.x + f0.y;
            psB += f1.x + f1.y;
        }
        psA += __shfl_xor_sync(0xffffffffu, psA, 1);
        psA += __shfl_xor_sync(0xffffffffu, psA, 2);
        psB += __shfl_xor_sync(0xffffffffu, psB, 1);
        psB += __shfl_xor_sync(0xffffffffu, psB, 2);
        lr0 = lr0 * aA + psA;
        lr1 = lr1 * aB + psB;
        mr0 = mnA;
        mr1 = mnB;
#pragma unroll
        for (int nt = 0; nt < 8; nt++) {
            acc_o[nt][0] *= aA;
            acc_o[nt][1] *= aA;
            acc_o[nt][2] *= aB;
            acc_o[nt][3] *= aB;
        }

        // ---- O += P V (single pass), V frags via ldmatrix.trans ----
#pragma unroll
        for (int ks = 0; ks < 4; ks++) {
            uint32_t vf[4][4];
#pragma unroll
            for (int j = 0; j < 4; j++) {
                int g = lane >> 3;
                int nt = 2 * j + (g >> 1);
                int kh = g & 1;
                int row = ks * 16 + kh * 8 + (lane & 7);
                ldm4t(vf[j], Vb + fswz(row, nt));
            }
#pragma unroll
            for (int nt = 0; nt < 8; nt++)
                mma16816h(acc_o[nt], pf[ks], &vf[nt >> 1][(nt & 1) * 2]);
        }
    }

    // ---- epilogue: normalize, store fp16 y ----
    float invA = 1.f / lr0, invB = 1.f / lr1;
    size_t rA = (size_t)(b * TT + q0 + wid * 16 + (lane >> 2));
    size_t rB = rA + 8;
#pragma unroll
    for (int nt = 0; nt < 8; nt++) {
        int col = h * 64 + nt * 8 + 2 * (lane & 3);
        *(uint32_t*)(y + rA * DD + col) =
            pack_half(acc_o[nt][0] * invA, acc_o[nt][1] * invA);
        *(uint32_t*)(y + rB * DD + col) =
            pack_half(acc_o[nt][2] * invB, acc_o[nt][3] * invB);
    }
}

// ---------------------------------------------------------------------------
// Launch
// ---------------------------------------------------------------------------
extern "C" void kernel_launch(void* const* d_in, const int* in_sizes, int n_in,
                              void* d_out, int out_size)
{
    const float* x     = (const float*)d_in[0];
    const float* W_qkv = (const float*)d_in[1];
    const float* b_qkv = (const float*)d_in[2];
    const float* W_o   = (const float*)d_in[3];
    const float* b_o   = (const float*)d_in[4];
    float* out = (float*)d_out;

    __half *qkv, *xh, *yh, *wqh, *woh;
    cudaGetSymbolAddress((void**)&qkv, g_qkv);
    cudaGetSymbolAddress((void**)&xh, g_x);
    cudaGetSymbolAddress((void**)&yh, g_y);
    cudaGetSymbolAddress((void**)&wqh, g_wqh);
    cudaGetSymbolAddress((void**)&woh, g_woh);

    cudaFuncSetAttribute(gemm_mma<true>, cudaFuncAttributeMaxDynamicSharedMemorySize,
                         GSMEM_BYTES);
    cudaFuncSetAttribute(gemm_mma<false>, cudaFuncAttributeMaxDynamicSharedMemorySize,
                         GSMEM_BYTES);
    cudaFuncSetAttribute(flash_tc, cudaFuncAttributeMaxDynamicSharedMemorySize,
                         FA_SMEM);

    // conversions
    convert_f32h<<<(MM * KK / 4 + 255) / 256, 256>>>(x, xh, MM * KK);
    transpose_h<<<dim3(TD3 / 32, KK / 32), dim3(32, 8)>>>(W_qkv, wqh, KK, TD3);
    transpose_h<<<dim3(DD / 32, KK / 32), dim3(32, 8)>>>(W_o, woh, KK, DD);

    // 1) QKV projection (fp16 single pass) -> fp16 qkv
    gemm_mma<true><<<dim3(TD3 / 128, MM / 128), 256, GSMEM_BYTES>>>(
        xh, wqh, b_qkv, nullptr, qkv, TD3);

    // 2) causal flash attention (fp16, BM=64, 128 thr, base-2 softmax) -> y
    flash_tc<<<dim3(TT / 64, BB * HH), 128, FA_SMEM>>>(qkv, yh);

    // 3) output projection (fp16 single pass) -> fp32 out
    gemm_mma<false><<<dim3(DD / 128, MM / 128), 256, GSMEM_BYTES>>>(
        yh, woh, b_o, out, nullptr, DD);
}

// round 12
// speedup vs baseline: 1.1979x; 1.1125x over previous
#include <cuda_runtime.h>
#include <cuda_bf16.h>
#include <cuda_fp16.h>
#include <cstdint>

// Problem constants (fixed by the reference)
#define BB 2
#define TT 2048
#define DD 1024
#define HH 16
#define DKK 64
#define TD3 3072    // 3*D
#define MM (BB*TT)  // 4096 rows
#define KK 1024     // GEMM K for both projections

// softmax scale folded with log2(e): exp(x*0.125) = 2^(x*0.125*log2e)
#define QK_SCALE 0.18033688011112042f

// ---------------------------------------------------------------------------
// Scratch (allocation-free rule: __device__ globals)
// ---------------------------------------------------------------------------
__device__ __half g_qkv[MM * TD3];           // qkv fp16
__device__ __half g_x[MM * KK];              // x fp16
__device__ __half g_y[MM * KK];              // attention out fp16
__device__ __half g_wqh[TD3 * KK];           // W_qkv^T fp16, [N][K]
__device__ __half g_woh[DD * KK];            // W_o^T fp16, [N][K]

// ---------------------------------------------------------------------------
// PTX helpers (plain sm_100-legal: cp.async + ldmatrix + mma.sync)
// ---------------------------------------------------------------------------
__device__ __forceinline__ uint32_t smem_u32(const void* p) {
    uint32_t a;
    asm("{ .reg .u64 t; cvta.to.shared.u64 t, %1; cvt.u32.u64 %0, t; }"
        : "=r"(a) : "l"(p));
    return a;
}
__device__ __forceinline__ void cp16(uint32_t dst, const void* src) {
    asm volatile("cp.async.cg.shared.global [%0], [%1], 16;" :: "r"(dst), "l"(src));
}
__device__ __forceinline__ void cp_commit() {
    asm volatile("cp.async.commit_group;" ::: "memory");
}
template <int N>
__device__ __forceinline__ void cp_wait() {
    asm volatile("cp.async.wait_group %0;" :: "n"(N) : "memory");
}
__device__ __forceinline__ void ldm4(uint32_t* r, uint32_t addr) {
    asm volatile("ldmatrix.sync.aligned.m8n8.x4.shared.b16 {%0,%1,%2,%3}, [%4];"
                 : "=r"(r[0]), "=r"(r[1]), "=r"(r[2]), "=r"(r[3]) : "r"(addr));
}
__device__ __forceinline__ void ldm4t(uint32_t* r, uint32_t addr) {
    asm volatile("ldmatrix.sync.aligned.m8n8.x4.trans.shared.b16 {%0,%1,%2,%3}, [%4];"
                 : "=r"(r[0]), "=r"(r[1]), "=r"(r[2]), "=r"(r[3]) : "r"(addr));
}
// fp16 MMA
__device__ __forceinline__ void mma16816h(float* c, const uint32_t* a,
                                          const uint32_t* b) {
    asm volatile(
        "mma.sync.aligned.m16n8k16.row.col.f32.f16.f16.f32 "
        "{%0,%1,%2,%3}, {%4,%5,%6,%7}, {%8,%9}, {%0,%1,%2,%3};"
        : "+f"(c[0]), "+f"(c[1]), "+f"(c[2]), "+f"(c[3])
        : "r"(a[0]), "r"(a[1]), "r"(a[2]), "r"(a[3]), "r"(b[0]), "r"(b[1]));
}
__device__ __forceinline__ uint32_t pack_half(float a, float b) {
    __half2 t = __floats2half2_rn(a, b);             // .x = a (low)
    return *(uint32_t*)&t;
}

// 128B-row XOR-8 swizzle (conflict-free for ldmatrix; proven in flash)
__device__ __forceinline__ uint32_t fswz(int row, int ch) {
    return (uint32_t)(row * 128 + ((ch ^ (row & 7)) << 4));
}

// ---------------------------------------------------------------------------
// Fused prep kernel: one launch does x convert + Wq transpose + Wo transpose.
// Blocks [0, NXB): convert x.  [NXB, NXB+NWQ): Wq.  [NXB+NWQ, +NWO): Wo.
// ---------------------------------------------------------------------------
#define NXB (MM * KK / 1024)            // 4096 blocks, 1024 elts each
#define NWQ ((TD3 / 32) * (KK / 32))    // 3072
#define NWO ((DD / 32) * (KK / 32))     // 1024

struct __align__(8) h4 { __half v[4]; };

__device__ __forceinline__ void transpose_tile(
    const float* __restrict__ W, __half* __restrict__ T,
    int K, int N, int n0, int k0, int tid)
{
    __shared__ float t[32][33];
    int tx = tid & 31, ty = tid >> 5;   // 32 x 8
#pragma unroll
    for (int i = ty; i < 32; i += 8)
        t[i][tx] = W[(size_t)(k0 + i) * N + n0 + tx];
    __syncthreads();
#pragma unroll
    for (int i = ty; i < 32; i += 8)
        T[(size_t)(n0 + i) * K + k0 + tx] = __float2half_rn(t[tx][i]);
}

__global__ __launch_bounds__(256) void prep_all(
    const float* __restrict__ x, __half* __restrict__ xh,
    const float* __restrict__ Wq, __half* __restrict__ wqh,
    const float* __restrict__ Wo, __half* __restrict__ woh)
{
    int bid = blockIdx.x;
    int tid = threadIdx.x;
    if (bid < NXB) {
        int i = (bid * 256 + tid) * 4;
        float4 v = *(const float4*)(x + i);
        h4 h;
        h.v[0] = __float2half_rn(v.x);
        h.v[1] = __float2half_rn(v.y);
        h.v[2] = __float2half_rn(v.z);
        h.v[3] = __float2half_rn(v.w);
        *(h4*)(xh + i) = h;
    } else if (bid < NXB + NWQ) {
        int b2 = bid - NXB;
        transpose_tile(Wq, wqh, KK, TD3, (b2 % (TD3 / 32)) * 32,
                       (b2 / (TD3 / 32)) * 32, tid);
    } else {
        int b3 = bid - NXB - NWQ;
        transpose_tile(Wo, woh, KK, DD, (b3 % (DD / 32)) * 32,
                       (b3 / (DD / 32)) * 32, tid);
    }
}

// ---------------------------------------------------------------------------
// fp16 single-pass GEMM: C = A @ B^T + bias.
// 128x128 tile / CTA, BK=64 (amortizes per-chunk phase-lock bubble),
// 3-stage cp.async, one sync per chunk.
// ---------------------------------------------------------------------------
#define TILE_B 16384                   // 128 rows * 128 B
#define STAGE_B (2 * TILE_B)           // A, B
#define GSTAGES 3
#define GSMEM_BYTES (GSTAGES * STAGE_B)  // 98304
#define NCHUNK (KK / 64)               // 16

__device__ __forceinline__ void load_stage(
    uint32_t sb, int s, int k0,
    const __half* __restrict__ A, const __half* __restrict__ Bh,
    int m0, int n0, int tid)
{
    uint32_t base = sb + (uint32_t)s * STAGE_B;
    const __half* srcs[2] = {A, Bh};
    int r0s[2] = {m0, n0};
#pragma unroll
    for (int t = 0; t < 2; t++) {
        const __half* p = srcs[t];
        int r0 = r0s[t];
        uint32_t tb = base + t * TILE_B;
#pragma unroll
        for (int i = 0; i < 4; i++) {
            int idx = tid + i * 256;       // 0..1023
            int row = idx >> 3;
            int ch = idx & 7;
            const void* g = p + (size_t)(r0 + row) * KK + k0 + ch * 8;
            cp16(tb + fswz(row, ch), g);
        }
    }
    cp_commit();
}

template <bool HALF_OUT>
__global__ __launch_bounds__(256, 2) void gemm_mma(
    const __half* __restrict__ A, const __half* __restrict__ Bh,
    const float* __restrict__ bias, float* __restrict__ C,
    __half* __restrict__ Ch, int N)
{
    extern __shared__ char smem[];
    uint32_t sb = smem_u32(smem);
    const int tid = threadIdx.x;
    const int wid = tid >> 5;
    const int lane = tid & 31;
    const int warp_m = wid >> 1;
    const int warp_n = wid & 1;
    const int n0 = blockIdx.x * 128;
    const int m0 = blockIdx.y * 128;

    float acc[2][8][4];
#pragma unroll
    for (int i = 0; i < 2; i++)
#pragma unroll
        for (int j = 0; j < 8; j++)
#pragma unroll
            for (int k = 0; k < 4; k++) acc[i][j][k] = 0.f;

    load_stage(sb, 0, 0, A, Bh, m0, n0, tid);
    load_stage(sb, 1, 64, A, Bh, m0, n0, tid);

    for (int c = 0; c < NCHUNK; c++) {
        if (c == NCHUNK - 1) cp_wait<0>(); else cp_wait<1>();
        __syncthreads();
        // load c+2 into buffer of c-1 (all warps finished it before barrier)
        if (c + 2 < NCHUNK)
            load_stage(sb, (c + 2) % GSTAGES, (c + 2) * 64, A, Bh, m0, n0, tid);

        uint32_t abase = sb + (uint32_t)(c % GSTAGES) * STAGE_B;
#pragma unroll
        for (int ks = 0; ks < 4; ks++) {
            uint32_t ah[2][4], bh[4][4];
#pragma unroll
            for (int mt = 0; mt < 2; mt++) {
                int row = warp_m * 32 + mt * 16 + (lane & 15);
                int ch = ks * 2 + (lane >> 4);
                ldm4(ah[mt], abase + fswz(row, ch));
            }
#pragma unroll
            for (int p = 0; p < 4; p++) {
                int row = warp_n * 64 + (p * 2 + (lane >> 4)) * 8 + (lane & 7);
                int ch = ks * 2 + ((lane >> 3) & 1);
                ldm4(bh[p], abase + TILE_B + fswz(row, ch));
            }
#pragma unroll
            for (int mt = 0; mt < 2; mt++)
#pragma unroll
                for (int nt = 0; nt < 8; nt++)
                    mma16816h(acc[mt][nt], ah[mt], &bh[nt >> 1][(nt & 1) * 2]);
        }
    }

#pragma unroll
    for (int mt = 0; mt < 2; mt++) {
        int m = m0 + warp_m * 32 + mt * 16 + (lane >> 2);
#pragma unroll
        for (int nt = 0; nt < 8; nt++) {
            int n = n0 + warp_n * 64 + nt * 8 + (lane & 3) * 2;
            float b0 = bias[n], b1 = bias[n + 1];
            float f0 = acc[mt][nt][0] + b0, f1 = acc[mt][nt][1] + b1;
            float f2 = acc[mt][nt][2] + b0, f3 = acc[mt][nt][3] + b1;
            if (HALF_OUT) {
                *(uint32_t*)(Ch + (size_t)m * N + n) = pack_half(f0, f1);
                *(uint32_t*)(Ch + (size_t)(m + 8) * N + n) = pack_half(f2, f3);
            } else {
                float2 o0 = {f0, f1}, o1 = {f2, f3};
                *(float2*)(C + (size_t)m * N + n) = o0;
                *(float2*)(C + (size_t)(m + 8) * N + n) = o1;
            }
        }
    }
}

// ---------------------------------------------------------------------------
// Tensor-core flash attention (causal), fp16 single-pass, base-2 softmax
// with h2exp2. BM=64 (4 warps, 128 threads) — 3 CTAs/SM without reg cap.
// ---------------------------------------------------------------------------
#define FA_TILE_B 8192                  // 64 rows * 128 B
#define FA_STAGE_B (2 * FA_TILE_B)      // K, V
#define FA_SMEM (2 * FA_STAGE_B)        // 32768

__device__ __forceinline__ void fa_load(
    uint32_t sb, int s, int k0, const __half* __restrict__ qkv,
    int b, int h, int tid)
{
    uint32_t base = sb + (uint32_t)s * FA_STAGE_B;
    int goff[2] = {1024, 2048};   // K, V
#pragma unroll
    for (int t = 0; t < 2; t++) {
        uint32_t tb = base + t * FA_TILE_B;
#pragma unroll
        for (int i = 0; i < 4; i++) {
            int idx = tid + i * 128;      // 0..511
            int row = idx >> 3;
            int ch = idx & 7;
            const void* g = qkv + (size_t)(b * TT + k0 + row) * TD3 + goff[t]
                          + h * 64 + ch * 8;
            cp16(tb + fswz(row, ch), g);
        }
    }
    cp_commit();
}

__global__ __launch_bounds__(128) void flash_tc(
    const __half* __restrict__ qkv, __half* __restrict__ y)
{
    extern __shared__ char smem[];
    uint32_t sb = smem_u32(smem);
    const int tid = threadIdx.x;
    const int wid = tid >> 5;          // 0..3
    const int lane = tid & 31;
    const int qt = (int)gridDim.x - 1 - (int)blockIdx.x;   // big tiles first
    const int bh = blockIdx.y;
    const int b = bh >> 4;
    const int h = bh & 15;
    const int q0 = qt * 64;

    const int ntile = qt + 1;
    fa_load(sb, 0, 0, qkv, b, h, tid);   // 1 group in flight

    // ---- Q fragments (fp16) straight from gmem ----
    uint32_t qf[4][4];
    {
        size_t r0g = (size_t)(b * TT + q0 + wid * 16 + (lane >> 2));
        const uint32_t* p0 = (const uint32_t*)(qkv + r0g * TD3 + h * 64);
        const uint32_t* p1 = (const uint32_t*)(qkv + (r0g + 8) * TD3 + h * 64);
        int c2 = lane & 3;
#pragma unroll
        for (int ks = 0; ks < 4; ks++) {
            qf[ks][0] = p0[ks * 8 + c2];
            qf[ks][1] = p1[ks * 8 + c2];
            qf[ks][2] = p0[ks * 8 + c2 + 4];
            qf[ks][3] = p1[ks * 8 + c2 + 4];
        }
    }

    float acc_o[8][4];
#pragma unroll
    for (int i = 0; i < 8; i++)
#pragma unroll
        for (int j = 0; j < 4; j++) acc_o[i][j] = 0.f;
    float mr0 = -1e30f, mr1 = -1e30f, lr0 = 0.f, lr1 = 0.f;

    for (int kt = 0; kt < ntile; kt++) {
        const int s = kt & 1;
        const int k0 = kt * 64;
        cp_wait<0>();
        __syncthreads();
        if (kt + 1 < ntile)
            fa_load(sb, s ^ 1, (kt + 1) * 64, qkv, b, h, tid);

        uint32_t Kb = sb + (uint32_t)s * FA_STAGE_B;
        uint32_t Vb = Kb + FA_TILE_B;

        // ---- S = Q K^T (single pass) ----
        float accs[8][4];
#pragma unroll
        for (int i = 0; i < 8; i++)
#pragma unroll
            for (int j = 0; j < 4; j++) accs[i][j] = 0.f;

#pragma unroll
        for (int ks = 0; ks < 4; ks++) {
            uint32_t kf[4][4];
#pragma unroll
            for (int j = 0; j < 4; j++) {
                int g = lane >> 3;
                int nt = 2 * j + (g >> 1);
                int kh = g & 1;
                int row = nt * 8 + (lane & 7);
                ldm4(kf[j], Kb + fswz(row, ks * 2 + kh));
            }
#pragma unroll
            for (int nt = 0; nt < 8; nt++)
                mma16816h(accs[nt], qf[ks], &kf[nt >> 1][(nt & 1) * 2]);
        }

        // ---- scale (log2 domain) + causal mask ----
        const int qrow0 = q0 + wid * 16 + (lane >> 2);
        const bool diag = (k0 + 63 > q0 + wid * 16);
#pragma unroll
        for (int nt = 0; nt < 8; nt++) {
#pragma unroll
            for (int c = 0; c < 4; c++) {
                float v = accs[nt][c] * QK_SCALE;
                if (diag) {
                    int col = k0 + nt * 8 + 2 * (lane & 3) + (c & 1);
                    int row = qrow0 + ((c >> 1) << 3);
                    if (col > row) v = -1e30f;
                }
                accs[nt][c] = v;
            }
        }

        // ---- online softmax (base-2) ----
        float mA = -1e30f, mB = -1e30f;
#pragma unroll
        for (int nt = 0; nt < 8; nt++) {
            mA = fmaxf(mA, fmaxf(accs[nt][0], accs[nt][1]));
            mB = fmaxf(mB, fmaxf(accs[nt][2], accs[nt][3]));
        }
        mA = fmaxf(mA, __shfl_xor_sync(0xffffffffu, mA, 1));
        mA = fmaxf(mA, __shfl_xor_sync(0xffffffffu, mA, 2));
        mB = fmaxf(mB, __shfl_xor_sync(0xffffffffu, mB, 1));
        mB = fmaxf(mB, __shfl_xor_sync(0xffffffffu, mB, 2));
        float mnA = fmaxf(mr0, mA), mnB = fmaxf(mr1, mB);
        float aA = exp2f(mr0 - mnA), aB = exp2f(mr1 - mnB);

        // P = 2^(s-m) in fp16x2 (h2exp2) — this IS the PV a-fragment.
        uint32_t pf[4][4];
        float psA = 0.f, psB = 0.f;
#pragma unroll
        for (int nt = 0; nt < 8; nt++) {
            __half2 e0 = h2exp2(__floats2half2_rn(accs[nt][0] - mnA,
                                                  accs[nt][1] - mnA));
            __half2 e1 = h2exp2(__floats2half2_rn(accs[nt][2] - mnB,
                                                  accs[nt][3] - mnB));
            pf[nt >> 1][(nt & 1) * 2 + 0] = *(uint32_t*)&e0;
            pf[nt >> 1][(nt & 1) * 2 + 1] = *(uint32_t*)&e1;
            float2 f0 = __half22float2(e0);
            float2 f1 = __half22float2(e1);
            psA += f0.x + f0.y;
            psB += f1.x + f1.y;
        }
        psA += __shfl_xor_sync(0xffffffffu, psA, 1);
        psA += __shfl_xor_sync(0xffffffffu, psA, 2);
        psB += __shfl_xor_sync(0xffffffffu, psB, 1);
        psB += __shfl_xor_sync(0xffffffffu, psB, 2);
        lr0 = lr0 * aA + psA;
        lr1 = lr1 * aB + psB;
        mr0 = mnA;
        mr1 = mnB;
#pragma unroll
        for (int nt = 0; nt < 8; nt++) {
            acc_o[nt][0] *= aA;
            acc_o[nt][1] *= aA;
            acc_o[nt][2] *= aB;
            acc_o[nt][3] *= aB;
        }

        // ---- O += P V (single pass), V frags via ldmatrix.trans ----
#pragma unroll
        for (int ks = 0; ks < 4; ks++) {
            uint32_t vf[4][4];
#pragma unroll
            for (int j = 0; j < 4; j++) {
                int g = lane >> 3;
                int nt = 2 * j + (g >> 1);
                int kh = g & 1;
                int row = ks * 16 + kh * 8 + (lane & 7);
                ldm4t(vf[j], Vb + fswz(row, nt));
            }
#pragma unroll
            for (int nt = 0; nt < 8; nt++)
                mma16816h(acc_o[nt], pf[ks], &vf[nt >> 1][(nt & 1) * 2]);
        }
    }

    // ---- epilogue: normalize, store fp16 y ----
    float invA = 1.f / lr0, invB = 1.f / lr1;
    size_t rA = (size_t)(b * TT + q0 + wid * 16 + (lane >> 2));
    size_t rB = rA + 8;
#pragma unroll
    for (int nt = 0; nt < 8; nt++) {
        int col = h * 64 + nt * 8 + 2 * (lane & 3);
        *(uint32_t*)(y + rA * DD + col) =
            pack_half(acc_o[nt][0] * invA, acc_o[nt][1] * invA);
        *(uint32_t*)(y + rB * DD + col) =
            pack_half(acc_o[nt][2] * invB, acc_o[nt][3] * invB);
    }
}

// ---------------------------------------------------------------------------
// Launch
// ---------------------------------------------------------------------------
extern "C" void kernel_launch(void* const* d_in, const int* in_sizes, int n_in,
                              void* d_out, int out_size)
{
    const float* x     = (const float*)d_in[0];
    const float* W_qkv = (const float*)d_in[1];
    const float* b_qkv = (const float*)d_in[2];
    const float* W_o   = (const float*)d_in[3];
    const float* b_o   = (const float*)d_in[4];
    float* out = (float*)d_out;

    __half *qkv, *xh, *yh, *wqh, *woh;
    cudaGetSymbolAddress((void**)&qkv, g_qkv);
    cudaGetSymbolAddress((void**)&xh, g_x);
    cudaGetSymbolAddress((void**)&yh, g_y);
    cudaGetSymbolAddress((void**)&wqh, g_wqh);
    cudaGetSymbolAddress((void**)&woh, g_woh);

    cudaFuncSetAttribute(gemm_mma<true>, cudaFuncAttributeMaxDynamicSharedMemorySize,
                         GSMEM_BYTES);
    cudaFuncSetAttribute(gemm_mma<false>, cudaFuncAttributeMaxDynamicSharedMemorySize,
                         GSMEM_BYTES);
    cudaFuncSetAttribute(flash_tc, cudaFuncAttributeMaxDynamicSharedMemorySize,
                         FA_SMEM);

    // 0) fused conversions (x convert + both W transposes, one launch)
    prep_all<<<NXB + NWQ + NWO, 256>>>(x, xh, W_qkv, wqh, W_o, woh);

    // 1) QKV projection (fp16 single pass, BK=64) -> fp16 qkv
    gemm_mma<true><<<dim3(TD3 / 128, MM / 128), 256, GSMEM_BYTES>>>(
        xh, wqh, b_qkv, nullptr, qkv, TD3);

    // 2) causal flash attention (fp16, BM=64, base-2 softmax) -> fp16 y
    flash_tc<<<dim3(TT / 64, BB * HH), 128, FA_SMEM>>>(qkv, yh);

    // 3) output projection (fp16 single pass, BK=64) -> fp32 out
    gemm_mma<false><<<dim3(DD / 128, MM / 128), 256, GSMEM_BYTES>>>(
        yh, woh, b_o, out, nullptr, DD);
}